// round 3
// baseline (speedup 1.0000x reference)
#include <cuda_runtime.h>
#include <cuda_bf16.h>

#define HASH_SIZE 256
#define OFFSET_SIZE 64

__global__ __launch_bounds__(256) void psh_kernel(
    const int*    __restrict__ coords,       // [N,3] int32
    const float4* __restrict__ hash_table,   // [256,256,256,8] f32 viewed as float4 pairs
    const int*    __restrict__ offset_table, // [64,64,64,3] int32
    const float*  __restrict__ m0,           // [3]
    const float*  __restrict__ m1,           // [3]
    float4*       __restrict__ out,          // [N,8] f32 viewed as float4 pairs
    int n)
{
    const float m0x = m0[0], m0y = m0[1], m0z = m0[2];
    const float m1x = m1[0], m1y = m1[1], m1z = m1[2];

    int i = blockIdx.x * blockDim.x + threadIdx.x;
    if (i >= n) return;

    // --- load coords (3x int32, dense stride-12B across the warp) ---
    const int c0 = coords[3 * i + 0];
    const int c1 = coords[3 * i + 1];
    const int c2 = coords[3 * i + 2];

    // --- offset-table index: (int)(c * m1) mod 64  (power-of-2 -> &63 == floor mod
    //     for the non-negative coords here; values are in [0,1024)) ---
    const int o0 = ((int)((float)c0 * m1x)) & (OFFSET_SIZE - 1);
    const int o1 = ((int)((float)c1 * m1y)) & (OFFSET_SIZE - 1);
    const int o2 = ((int)((float)c2 * m1z)) & (OFFSET_SIZE - 1);
    const int obase = ((((o0 << 6) | o1) << 6) | o2) * 3;

    // --- gather offsets (3 MB table -> L2-resident) ---
    const int f0 = offset_table[obase + 0];
    const int f1 = offset_table[obase + 1];
    const int f2 = offset_table[obase + 2];

    // --- hash index: ((int)(c * m0) + off) mod 256  (operands >= 0 -> & is floor mod) ---
    const int h0 = (((int)((float)c0 * m0x)) + f0) & (HASH_SIZE - 1);
    const int h1 = (((int)((float)c1 * m0y)) + f1) & (HASH_SIZE - 1);
    const int h2 = (((int)((float)c2 * m0z)) + f2) & (HASH_SIZE - 1);

    // row index into [256^3] rows of 8 floats; as float4 units: *2
    const long long hidx = (long long)((((h0 << 8) | h1) << 8) | h2) * 2;

    // --- gather 32B hash row (one DRAM sector), pure copy to output ---
    const float4 a = hash_table[hidx + 0];
    const float4 b = hash_table[hidx + 1];

    const long long ob = 2ll * i;
    out[ob + 0] = a;
    out[ob + 1] = b;
}

extern "C" void kernel_launch(void* const* d_in, const int* in_sizes, int n_in,
                              void* d_out, int out_size) {
    const int*    coords       = (const int*)d_in[0];
    const float4* hash_table   = (const float4*)d_in[1];
    const int*    offset_table = (const int*)d_in[2];
    const float*  m0           = (const float*)d_in[3];
    const float*  m1           = (const float*)d_in[4];
    float4*       out          = (float4*)d_out;

    const int n = in_sizes[0] / 3;  // coords element count = N*3
    const int threads = 256;
    const int blocks = (n + threads - 1) / threads;
    psh_kernel<<<blocks, threads>>>(coords, hash_table, offset_table, m0, m1, out, n);
}

// round 5
// speedup vs baseline: 1.0364x; 1.0364x over previous
#include <cuda_runtime.h>
#include <cuda_bf16.h>

#define HASH_SIZE 256
#define OFFSET_SIZE 64

// L2 evict-last cache policy (created once per thread, uniform value) for the
// 3MB offset table, so the streaming hash gathers don't evict it.
__device__ __forceinline__ long long make_evict_last_policy() {
    long long p;
    asm("createpolicy.fractional.L2::evict_last.b64 %0, 1.0;" : "=l"(p));
    return p;
}

__device__ __forceinline__ int ldg_hint_s32(const int* ptr, long long pol) {
    int v;
    asm volatile("ld.global.L2::cache_hint.s32 %0, [%1], %2;"
                 : "=r"(v) : "l"(ptr), "l"(pol));
    return v;
}

__global__ __launch_bounds__(256) void psh_kernel(
    const int*    __restrict__ coords,       // [N,3] int32
    const float4* __restrict__ hash_table,   // [256,256,256,8] f32 as float4 pairs
    const int*    __restrict__ offset_table, // [64,64,64,3] int32
    const float*  __restrict__ m0,           // [3]
    const float*  __restrict__ m1,           // [3]
    float4*       __restrict__ out,          // [N,8] f32 as float4 pairs
    int n)
{
    const float m0x = m0[0], m0y = m0[1], m0z = m0[2];
    const float m1x = m1[0], m1y = m1[1], m1z = m1[2];

    int i = blockIdx.x * blockDim.x + threadIdx.x;
    if (i >= n) return;

    const long long pol = make_evict_last_policy();

    // --- coords: dense, read-once -> streaming loads ---
    const int c0 = __ldcs(&coords[3 * i + 0]);
    const int c1 = __ldcs(&coords[3 * i + 1]);
    const int c2 = __ldcs(&coords[3 * i + 2]);

    // --- offset-table index: (int)(c * m1) & 63 (non-negative -> floor mod) ---
    const int o0 = ((int)((float)c0 * m1x)) & (OFFSET_SIZE - 1);
    const int o1 = ((int)((float)c1 * m1y)) & (OFFSET_SIZE - 1);
    const int o2 = ((int)((float)c2 * m1z)) & (OFFSET_SIZE - 1);
    const int obase = ((((o0 << 6) | o1) << 6) | o2) * 3;

    // --- offset gather: 3MB table, pin in L2 with evict_last policy ---
    const int f0 = ldg_hint_s32(&offset_table[obase + 0], pol);
    const int f1 = ldg_hint_s32(&offset_table[obase + 1], pol);
    const int f2 = ldg_hint_s32(&offset_table[obase + 2], pol);

    // --- hash index: ((int)(c * m0) + off) & 255 ---
    const int h0 = (((int)((float)c0 * m0x)) + f0) & (HASH_SIZE - 1);
    const int h1 = (((int)((float)c1 * m0y)) + f1) & (HASH_SIZE - 1);
    const int h2 = (((int)((float)c2 * m0z)) + f2) & (HASH_SIZE - 1);

    const long long hidx = (long long)((((h0 << 8) | h1) << 8) | h2) * 2;

    // --- hash gather: 512MB random, ~no reuse -> streaming (don't pollute L2) ---
    const float4 a = __ldcs(&hash_table[hidx + 0]);
    const float4 b = __ldcs(&hash_table[hidx + 1]);

    // --- output: write-once -> streaming stores ---
    const long long ob = 2ll * i;
    __stcs(&out[ob + 0], a);
    __stcs(&out[ob + 1], b);
}

extern "C" void kernel_launch(void* const* d_in, const int* in_sizes, int n_in,
                              void* d_out, int out_size) {
    const int*    coords       = (const int*)d_in[0];
    const float4* hash_table   = (const float4*)d_in[1];
    const int*    offset_table = (const int*)d_in[2];
    const float*  m0           = (const float*)d_in[3];
    const float*  m1           = (const float*)d_in[4];
    float4*       out          = (float4*)d_out;

    const int n = in_sizes[0] / 3;  // coords element count = N*3
    const int threads = 256;
    const int blocks = (n + threads - 1) / threads;
    psh_kernel<<<blocks, threads>>>(coords, hash_table, offset_table, m0, m1, out, n);
}